// round 5
// baseline (speedup 1.0000x reference)
#include <cuda_runtime.h>
#include <cstdint>

#define NH       4096
#define NH4      1024
#define OBS      512
#define NSTEPS   63
#define NOUT     128
#define CMB      4608
#define CMB4     1152

#define GRID     147
#define NW       14                   // warps per CTA
#define NTHREADS (NW * 32)            // 448
#define RPB      28                   // rows per CTA (2 per warp)
#define SW       13                   // weight rows cached in SMEM (row 2w for w<13)

// dynamic smem: [SW rows of Wf][v buffer NH][dt 64]  = 229,632 B (< 232,448 cap)
#define SMEM_FLOATS (SW * NH + NH + 64)
#define SMEM_BYTES  (SMEM_FLOATS * 4)

__device__ __align__(16) float gV[2][NH];   // stage-input ping-pong
__device__ __align__(16) float gHn[NH];     // h_new
__device__ unsigned g_flags[GRID];          // per-CTA monotonic barrier flags (zero-init)

// ---- flag-array grid barrier: parallel arrivals, no atomic serialization ----
__device__ __forceinline__ void grid_arrive(unsigned target) {
    __syncthreads();                         // all CTA stores done
    if (threadIdx.x == 0) {
        asm volatile("st.release.gpu.u32 [%0], %1;"
                     :: "l"(g_flags + blockIdx.x), "r"(target) : "memory");
    }
}

__device__ __forceinline__ void grid_wait(unsigned target) {
    if (threadIdx.x < 32) {
        const int lane = threadIdx.x;
        bool done;
        do {
            bool ok = true;
            #pragma unroll
            for (int j = 0; j < 5; ++j) {
                int idx = lane + 32 * j;
                unsigned f = target;
                if (idx < GRID) {
                    asm volatile("ld.relaxed.gpu.u32 %0, [%1];"
                                 : "=r"(f) : "l"(g_flags + idx));
                }
                ok &= ((int)(f - target) >= 0);
            }
            done = __all_sync(0xFFFFFFFFu, ok);
        } while (!done);
        asm volatile("fence.acq_rel.gpu;" ::: "memory");
    }
    __syncthreads();
}

__device__ __forceinline__ float warp_sum(float v) {
    #pragma unroll
    for (int o = 16; o; o >>= 1) v += __shfl_xor_sync(0xffffffffu, v, o);
    return v;
}

#define FMA4(A, Q, B) \
    { (A).x = fmaf((Q).x, (B).x, (A).x); (A).y = fmaf((Q).y, (B).y, (A).y); \
      (A).z = fmaf((Q).z, (B).z, (A).z); (A).w = fmaf((Q).w, (B).w, (A).w); }

__global__ void __launch_bounds__(NTHREADS, 1)
ode_rnn_kernel(const float* __restrict__ x,
               const float* __restrict__ h0,
               const float* __restrict__ t,
               const float* __restrict__ Wf,
               const float* __restrict__ bf,
               const float* __restrict__ Wi,
               const float* __restrict__ bi,
               const float* __restrict__ Wo,
               const float* __restrict__ bo,
               float* __restrict__ out)
{
    extern __shared__ float smem[];
    float4* wsm   = (float4*)smem;               // SW * NH4 float4 (weight rows)
    float4* vsm   = (float4*)(smem + SW * NH);   // NH4 float4 (stage vector)
    float*  dtbuf = smem + SW * NH + NH;         // 64 floats

    const int tid  = threadIdx.x;
    const int w    = tid >> 5;
    const int lane = tid & 31;
    const int base = blockIdx.x * RPB;

    // launch-epoch base for monotonic barrier counts (replay-safe)
    unsigned barcnt;
    asm volatile("ld.relaxed.gpu.u32 %0, [%1];"
                 : "=r"(barcnt) : "l"(g_flags + blockIdx.x));

    // warp w owns rows rA = base+2w (SMEM for w<13), rB = base+2w+1 (L2)
    const int rA = base + 2 * w;
    const int rB = rA + 1;
    const int cA = min(rA, NH - 1);
    const int cB = min(rB, NH - 1);

    const float4* Wf4 = (const float4*)Wf;
    const float4* pA  = Wf4 + (size_t)cA * NH4;
    const float4* pB  = Wf4 + (size_t)cB * NH4;

    // ---- SMEM weight preload: rows base+2s for s=0..12 ----
    for (int idx = tid; idx < SW * NH4; idx += NTHREADS) {
        int slot   = idx >> 10;
        int within = idx & 1023;
        int gr     = min(base + 2 * slot, NH - 1);
        wsm[idx]   = __ldg(Wf4 + (size_t)gr * NH4 + within);
    }
    if (tid < NSTEPS) dtbuf[tid] = __ldg(t + tid + 1) - __ldg(t + tid);

    // small register cache: first quarter of rowB (chunks 0..7)
    float4 cacheB[8];
    #pragma unroll
    for (int k = 0; k < 8; ++k) cacheB[k] = __ldg(pB + lane + 32 * k);

    // per-lane RK4 state: lane 0 -> rA, lane 1 -> rB
    float hh = 0.f, bfv = 0.f;
    if (lane < 2) {
        int r = min(rA + lane, NH - 1);
        hh  = __ldg(h0 + r);
        bfv = __ldg(bf + r);
        if (rA + lane < NH) gV[0][rA + lane] = hh;
    }

    const float4* waS = wsm + (size_t)w * NH4;   // smem rowA (w<13)

    // rings: rb covers rowB chunks 8..31 ; ra (w==13 only) covers rowA chunks 0..31
    float4 rb[4], ra[4];

    // initial barrier; prefetch stage-0 rings under the wait
    ++barcnt;
    grid_arrive(barcnt);
    #pragma unroll
    for (int j = 0; j < 4; ++j) rb[j] = __ldg(pB + lane + 32 * (8 + j));
    if (w == NW - 1) {
        #pragma unroll
        for (int j = 0; j < 4; ++j) ra[j] = __ldg(pA + lane + 32 * j);
    }
    grid_wait(barcnt);

    int p = 0;
    float k1 = 0.f, k2 = 0.f, k3 = 0.f;

    for (int s = 0; s < NSTEPS; ++s) {
        const float dt   = dtbuf[s];
        const float half = 0.5f * dt;

        #pragma unroll 1
        for (int u = 0; u < 4; ++u) {
            const float4* vsrc = (const float4*)gV[p];

            // cooperative v fill (coherent L2 reads)
            for (int i = tid; i < NH4; i += NTHREADS)
                vsm[i] = __ldcg(vsrc + i);
            __syncthreads();

            float4 A0 = make_float4(0.f,0.f,0.f,0.f);
            float4 A1 = A0;

            if (w < NW - 1) {
                #pragma unroll
                for (int k = 0; k < 8; ++k) {
                    const int i = lane + 32 * k;
                    float4 b = vsm[i];
                    FMA4(A0, waS[i], b);
                    FMA4(A1, cacheB[k], b);
                }
                #pragma unroll
                for (int k = 8; k < 32; ++k) {
                    const int i = lane + 32 * k;
                    float4 b = vsm[i];
                    float4 q = rb[k & 3];
                    if (k < 28) rb[k & 3] = __ldg(pB + i + 128);
                    FMA4(A0, waS[i], b);
                    FMA4(A1, q, b);
                }
            } else {
                #pragma unroll
                for (int k = 0; k < 8; ++k) {
                    const int i = lane + 32 * k;
                    float4 b  = vsm[i];
                    float4 qa = ra[k & 3];
                    ra[k & 3] = __ldg(pA + i + 128);
                    FMA4(A0, qa, b);
                    FMA4(A1, cacheB[k], b);
                }
                #pragma unroll
                for (int k = 8; k < 32; ++k) {
                    const int i = lane + 32 * k;
                    float4 b  = vsm[i];
                    float4 qa = ra[k & 3];
                    float4 qb = rb[k & 3];
                    if (k < 28) {
                        ra[k & 3] = __ldg(pA + i + 128);
                        rb[k & 3] = __ldg(pB + i + 128);
                    }
                    FMA4(A0, qa, b);
                    FMA4(A1, qb, b);
                }
            }

            float zA = warp_sum((A0.x + A0.y) + (A0.z + A0.w));
            float zB = warp_sum((A1.x + A1.y) + (A1.z + A1.w));

            float z  = (lane == 0) ? zA : zB;
            float kk = tanhf(z + bfv);

            float vn;
            if (u == 0)      { k1 = kk; vn = hh + half * kk; }
            else if (u == 1) { k2 = kk; vn = hh + half * kk; }
            else if (u == 2) { k3 = kk; vn = hh + dt * kk; }
            else {
                hh = hh + (dt * (1.0f / 6.0f)) * (k1 + 2.0f * k2 + 2.0f * k3 + kk);
                vn = hh;
            }
            if (lane < 2 && (rA + lane) < NH) gV[p ^ 1][rA + lane] = vn;

            // arrive, prefetch next stage's rings under the wait, then wait
            ++barcnt;
            grid_arrive(barcnt);
            #pragma unroll
            for (int j = 0; j < 4; ++j) rb[j] = __ldg(pB + lane + 32 * (8 + j));
            if (w == NW - 1) {
                #pragma unroll
                for (int j = 0; j < 4; ++j) ra[j] = __ldg(pA + lane + 32 * j);
            }
            grid_wait(barcnt);
            p ^= 1;
        }
    }
    // gV[p] == hT

    // ---- i2h: h_new = tanh(W_i2h @ [x; hT] + b_i2h) ----
    {
        float4* cmb = (float4*)smem;                 // reuse weight SMEM
        const float4* xs = (const float4*)x;
        const float4* hs = (const float4*)gV[p];
        for (int i = tid; i < CMB4; i += NTHREADS)
            cmb[i] = (i < OBS / 4) ? __ldg(xs + i) : __ldcg(hs + (i - OBS / 4));
        __syncthreads();

        const float4* Wi4 = (const float4*)Wi;
        const float4* q0 = Wi4 + (size_t)cA * CMB4;
        const float4* q1 = Wi4 + (size_t)cB * CMB4;

        float4 A0 = make_float4(0.f,0.f,0.f,0.f);
        float4 A1 = A0;
        #pragma unroll 4
        for (int k = 0; k < 36; ++k) {               // CMB4/32 = 36
            const int i = lane + 32 * k;
            float4 b = cmb[i];
            FMA4(A0, __ldg(q0 + i), b);
            FMA4(A1, __ldg(q1 + i), b);
        }
        float zA = warp_sum((A0.x + A0.y) + (A0.z + A0.w));
        float zB = warp_sum((A1.x + A1.y) + (A1.z + A1.w));

        if (lane < 2) {
            int r = rA + lane;
            if (r < NH) {
                float z  = (lane == 0) ? zA : zB;
                float hn = tanhf(z + __ldg(bi + r));
                gHn[r] = hn;
                out[NOUT + r] = hn;
            }
        }
    }
    ++barcnt;
    grid_arrive(barcnt);
    grid_wait(barcnt);

    // ---- h2o: out[0..127] = W_h2o @ h_new + b_h2o (one row per warp) ----
    {
        const int gw = blockIdx.x * NW + w;
        if (gw < NOUT) {
            const float4* wr = (const float4*)Wo + (size_t)gw * NH4;
            const float4* hv = (const float4*)gHn;
            float4 A = make_float4(0.f,0.f,0.f,0.f);
            #pragma unroll 4
            for (int k = 0; k < 32; ++k) {
                const int i = lane + 32 * k;
                FMA4(A, __ldg(wr + i), __ldcg(hv + i));
            }
            float z = warp_sum((A.x + A.y) + (A.z + A.w));
            if (lane == 0) out[gw] = z + __ldg(bo + gw);
        }
    }
}

extern "C" void kernel_launch(void* const* d_in, const int* in_sizes, int n_in,
                              void* d_out, int out_size)
{
    const float* x   = (const float*)d_in[0];
    const float* h0  = (const float*)d_in[1];
    const float* t   = (const float*)d_in[2];
    const float* Wf  = (const float*)d_in[3];
    const float* bf  = (const float*)d_in[4];
    const float* Wi  = (const float*)d_in[5];
    const float* bi  = (const float*)d_in[6];
    const float* Wo  = (const float*)d_in[7];
    const float* bo  = (const float*)d_in[8];
    float* out = (float*)d_out;

    cudaFuncSetAttribute(ode_rnn_kernel,
                         cudaFuncAttributeMaxDynamicSharedMemorySize, SMEM_BYTES);
    ode_rnn_kernel<<<GRID, NTHREADS, SMEM_BYTES>>>(x, h0, t, Wf, bf, Wi, bi, Wo, bo, out);
}

// round 6
// speedup vs baseline: 1.8322x; 1.8322x over previous
#include <cuda_runtime.h>
#include <cstdint>

#define NH     4096
#define NH4    1024
#define OBS    512
#define NSTAGE 252                 // 63 RK4 steps * 4 stages
#define NOUT   128
#define CMB4   1152

#define GRID   147
#define NCW    14                  // compute warps
#define NTHREADS 512               // 14 compute + 2 producer warps
#define RPB    28                  // rows per CTA
#define SW     13                  // weight rows in SMEM
#define GF4    147                 // float4 per group (21 chunks x 7)
#define NG     7                   // groups per stage (7*147 = 1029 f4 = 4116 floats)

// smem byte offsets
#define OFF_WSM   0                // 13*4096*4      = 212992
#define OFF_VSM   212992           // 1029 float4    = 16464
#define OFF_ZBUF  229456           // 28 floats      = 112
#define OFF_DT    229568           // 63 floats      -> pad 256
#define OFF_CNT   229824           // 7 u32          -> pad 32
#define OFF_E     229856           // 1 u32
#define SMEM_BYTES 229888

__device__ __align__(16) float gV[2][4128];   // padded: 147*28 = 4116 floats used
__device__ __align__(16) float gHn[4128];
__device__ unsigned gFlag[GRID];              // per-CTA monotonic publish count

__device__ __forceinline__ unsigned smem_u32(const void* p) {
    return (unsigned)__cvta_generic_to_shared(p);
}

__device__ __forceinline__ void cnt_spin(unsigned saddr, unsigned target) {
    unsigned v;
    do {
        asm volatile("ld.acquire.cta.shared::cta.b32 %0, [%1];"
                     : "=r"(v) : "r"(saddr) : "memory");
    } while ((int)(v - target) < 0);
}

__device__ __forceinline__ void cnt_release(unsigned saddr, unsigned v) {
    asm volatile("st.release.cta.shared::cta.b32 [%0], %1;"
                 :: "r"(saddr), "r"(v) : "memory");
}

__device__ __forceinline__ float warp_sum(float v) {
    #pragma unroll
    for (int o = 16; o; o >>= 1) v += __shfl_xor_sync(0xffffffffu, v, o);
    return v;
}

#define FMA4(A, Q, B) \
    { (A).x = fmaf((Q).x, (B).x, (A).x); (A).y = fmaf((Q).y, (B).y, (A).y); \
      (A).z = fmaf((Q).z, (B).z, (A).z); (A).w = fmaf((Q).w, (B).w, (A).w); }

// producer: wait for the 21 chunk-flags of group g, stream group into vsm, release counter
__device__ __forceinline__ void fill_group(int g, int lane, const float4* __restrict__ src,
                                           float4* vsm4, unsigned cntA,
                                           unsigned flagTgt, unsigned fillVal) {
    if (lane < 21) {
        const unsigned* fp = gFlag + 21 * g + lane;
        unsigned v;
        do {
            asm volatile("ld.acquire.gpu.u32 %0, [%1];" : "=r"(v) : "l"(fp) : "memory");
        } while ((int)(v - flagTgt) < 0);
    }
    __syncwarp();
    #pragma unroll
    for (int jj = 0; jj < 5; ++jj) {
        int o = lane + 32 * jj;
        if (o < GF4) {
            int i = GF4 * g + o;
            vsm4[i] = __ldcg(src + i);
        }
    }
    __syncwarp();
    if (lane == 0) cnt_release(cntA + 4u * (unsigned)g, fillVal);
}

// publisher (one lane): copy 7 float4 from zbuf to dst chunk, fence, bump flag
__device__ __forceinline__ void publish_chunk(float4* dst, const float4* zb,
                                              unsigned* flagp, unsigned newFlag) {
    #pragma unroll
    for (int j = 0; j < 7; ++j) dst[j] = zb[j];
    asm volatile("fence.acq_rel.gpu;" ::: "memory");
    asm volatile("st.relaxed.gpu.u32 [%0], %1;" :: "l"(flagp), "r"(newFlag) : "memory");
}

__global__ void __launch_bounds__(NTHREADS, 1)
ode_rnn_kernel(const float* __restrict__ x,
               const float* __restrict__ h0,
               const float* __restrict__ t,
               const float* __restrict__ Wf,
               const float* __restrict__ bf,
               const float* __restrict__ Wi,
               const float* __restrict__ bi,
               const float* __restrict__ Wo,
               const float* __restrict__ bo,
               float* __restrict__ out)
{
    extern __shared__ char smem[];
    float4*  wsm   = (float4*)(smem + OFF_WSM);
    float4*  vsm4  = (float4*)(smem + OFF_VSM);
    float*   zbuf  = (float*) (smem + OFF_ZBUF);
    float*   dtbuf = (float*) (smem + OFF_DT);
    unsigned* sE   = (unsigned*)(smem + OFF_E);
    const unsigned cntA = smem_u32(smem + OFF_CNT);

    const int tid  = threadIdx.x;
    const int w    = tid >> 5;
    const int lane = tid & 31;
    const int cb   = blockIdx.x;
    const int base = cb * RPB;

    const float4* Wf4 = (const float4*)Wf;

    // ---- startup init ----
    for (int idx = tid; idx < SW * NH4; idx += NTHREADS) {
        int slot   = idx >> 10;
        int within = idx & 1023;
        int gr     = min(base + 2 * slot, NH - 1);     // smem rows: base+2s (rowA of warp s)
        wsm[idx]   = __ldg(Wf4 + (size_t)gr * NH4 + within);
    }
    if (tid < NSTAGE / 4) dtbuf[tid] = __ldg(t + tid + 1) - __ldg(t + tid);
    if (tid < NG) ((unsigned*)(smem + OFF_CNT))[tid] = 0u;
    if (tid == 0) {
        unsigned e;
        asm volatile("ld.relaxed.gpu.u32 %0, [%1];" : "=r"(e) : "l"(gFlag + cb) : "memory");
        sE[0] = e;
    }
    __syncthreads();                                    // startup barrier

    // =====================  PRODUCER WARPS (w14, w15)  =====================
    if (w >= NCW) {
        const bool isA = (w == NCW);                    // w14: groups 0,2,4,6 + publisher
        const unsigned E = sE[0];
        unsigned* myFlag = gFlag + cb;
        const float4* zb4 = (const float4*)zbuf;

        // init publish: h0 chunk -> gV[0]
        if (isA) {
            if (lane == 0) {
                float4* dst = (float4*)gV[0] + 7 * cb;
                const float4* h04 = (const float4*)h0;
                #pragma unroll
                for (int j = 0; j < 7; ++j) {
                    int idx = 7 * cb + j;
                    float4 hv = (idx < NH4) ? __ldg(h04 + idx) : make_float4(0.f,0.f,0.f,0.f);
                    dst[j] = hv;
                }
                asm volatile("fence.acq_rel.gpu;" ::: "memory");
                asm volatile("st.relaxed.gpu.u32 [%0], %1;" :: "l"(myFlag), "r"(E + 1) : "memory");
            }
            __syncwarp();
        }

        for (int sg = 0; sg < NSTAGE; ++sg) {
            const float4* src = (const float4*)gV[sg & 1];
            const unsigned ft = E + 1 + (unsigned)sg;
            const unsigned fv = (unsigned)sg + 1;
            if (isA) {
                fill_group(0, lane, src, vsm4, cntA, ft, fv);
                fill_group(2, lane, src, vsm4, cntA, ft, fv);
                fill_group(4, lane, src, vsm4, cntA, ft, fv);
                fill_group(6, lane, src, vsm4, cntA, ft, fv);
            } else {
                fill_group(1, lane, src, vsm4, cntA, ft, fv);
                fill_group(3, lane, src, vsm4, cntA, ft, fv);
                fill_group(5, lane, src, vsm4, cntA, ft, fv);
            }
            __syncthreads();                            // compute done + zbuf ready
            if (isA) {
                if (lane == 0)
                    publish_chunk((float4*)gV[(sg + 1) & 1] + 7 * cb, zb4,
                                  myFlag, E + 2 + (unsigned)sg);
                __syncwarp();
            }
        }

        // i2h: deliver hT (publish 252 lives in gV[0])
        {
            const float4* src = (const float4*)gV[0];
            const unsigned ft = E + 253, fv = 253;
            if (isA) {
                fill_group(0, lane, src, vsm4, cntA, ft, fv);
                fill_group(2, lane, src, vsm4, cntA, ft, fv);
                fill_group(4, lane, src, vsm4, cntA, ft, fv);
                fill_group(6, lane, src, vsm4, cntA, ft, fv);
            } else {
                fill_group(1, lane, src, vsm4, cntA, ft, fv);
                fill_group(3, lane, src, vsm4, cntA, ft, fv);
                fill_group(5, lane, src, vsm4, cntA, ft, fv);
            }
            __syncthreads();
            if (isA) {
                if (lane == 0)
                    publish_chunk((float4*)gHn + 7 * cb, zb4, myFlag, E + 254);
                __syncwarp();
            }
        }

        // h2o: deliver h_new to CTAs that compute an output row
        if (cb < NOUT) {
            const float4* src = (const float4*)gHn;
            const unsigned ft = E + 254, fv = 254;
            if (isA) {
                fill_group(0, lane, src, vsm4, cntA, ft, fv);
                fill_group(2, lane, src, vsm4, cntA, ft, fv);
                fill_group(4, lane, src, vsm4, cntA, ft, fv);
                fill_group(6, lane, src, vsm4, cntA, ft, fv);
            } else {
                fill_group(1, lane, src, vsm4, cntA, ft, fv);
                fill_group(3, lane, src, vsm4, cntA, ft, fv);
                fill_group(5, lane, src, vsm4, cntA, ft, fv);
            }
        }
        return;
    }

    // =====================  COMPUTE WARPS (w0..w13)  =====================
    const int rA = base + 2 * w;                        // SMEM row (w<13), L2 for w13
    const int rB = rA + 1;                              // L2 row
    const int cAi = min(rA, NH - 1);
    const int cBi = min(rB, NH - 1);
    const float4* pA  = Wf4 + (size_t)cAi * NH4;
    const float4* pB  = Wf4 + (size_t)cBi * NH4;
    const float4* waS = wsm + (size_t)w * NH4;

    float hh = 0.f, bfv = 0.f;
    if (lane < 2) {
        int r = min(rA + lane, NH - 1);
        hh  = __ldg(h0 + r);
        bfv = __ldg(bf + r);
    }

    // prefetch rings for group 0
    float4 rb[5], ra[5];
    #pragma unroll
    for (int jj = 0; jj < 5; ++jj) {
        int o = lane + 32 * jj;
        rb[jj] = (o < GF4) ? __ldg(pB + o) : make_float4(0.f,0.f,0.f,0.f);
        if (w == NCW - 1)
            ra[jj] = (o < GF4) ? __ldg(pA + o) : make_float4(0.f,0.f,0.f,0.f);
    }

    float k1 = 0.f, k2 = 0.f, k3 = 0.f;

    #pragma unroll 1
    for (int sg = 0; sg < NSTAGE; ++sg) {
        const float dt   = dtbuf[sg >> 2];
        const int   u    = sg & 3;
        const unsigned target = (unsigned)sg + 1;

        float4 A0 = make_float4(0.f,0.f,0.f,0.f);
        float4 A1 = A0;

        #pragma unroll 1
        for (int g = 0; g < NG; ++g) {
            cnt_spin(cntA + 4u * (unsigned)g, target);
            if (w < NCW - 1) {
                #pragma unroll
                for (int jj = 0; jj < 5; ++jj) {
                    int o = lane + 32 * jj;
                    int i = GF4 * g + o;
                    if (o < GF4 && i < NH4) {
                        float4 b = vsm4[i];
                        FMA4(A0, waS[i], b);
                        FMA4(A1, rb[jj], b);
                    }
                    int nx = (g == NG - 1) ? o : (i + GF4);
                    if (o < GF4 && nx < NH4)
                        rb[jj] = __ldg(pB + nx);
                }
            } else {
                #pragma unroll
                for (int jj = 0; jj < 5; ++jj) {
                    int o = lane + 32 * jj;
                    int i = GF4 * g + o;
                    if (o < GF4 && i < NH4) {
                        float4 b = vsm4[i];
                        FMA4(A0, ra[jj], b);
                        FMA4(A1, rb[jj], b);
                    }
                    int nx = (g == NG - 1) ? o : (i + GF4);
                    if (o < GF4 && nx < NH4) {
                        ra[jj] = __ldg(pA + nx);
                        rb[jj] = __ldg(pB + nx);
                    }
                }
            }
        }

        float zA = warp_sum((A0.x + A0.y) + (A0.z + A0.w));
        float zB = warp_sum((A1.x + A1.y) + (A1.z + A1.w));

        float z  = (lane == 0) ? zA : zB;
        float kk = tanhf(z + bfv);

        float vn;
        const float half = 0.5f * dt;
        if (u == 0)      { k1 = kk; vn = hh + half * kk; }
        else if (u == 1) { k2 = kk; vn = hh + half * kk; }
        else if (u == 2) { k3 = kk; vn = hh + dt * kk; }
        else {
            hh = hh + (dt * (1.0f / 6.0f)) * (k1 + 2.0f * k2 + 2.0f * k3 + kk);
            vn = hh;
        }
        if (lane < 2) zbuf[2 * w + lane] = vn;

        __syncthreads();                                // zbuf ready; vsm consumable
    }

    // ---- i2h: h_new = tanh(W_i2h @ [x; hT] + b_i2h) ----
    {
        const float4* Wi4 = (const float4*)Wi;
        const float4* qA = Wi4 + (size_t)cAi * CMB4;
        const float4* qB = Wi4 + (size_t)cBi * CMB4;
        const float4* x4 = (const float4*)x;

        float4 A0 = make_float4(0.f,0.f,0.f,0.f);
        float4 A1 = A0;

        // x part (128 float4), no dependency
        #pragma unroll
        for (int jj = 0; jj < 4; ++jj) {
            int i = lane + 32 * jj;
            float4 b = __ldg(x4 + i);
            FMA4(A0, __ldg(qA + i), b);
            FMA4(A1, __ldg(qB + i), b);
        }
        // hT part via producer groups
        #pragma unroll 1
        for (int g = 0; g < NG; ++g) {
            cnt_spin(cntA + 4u * (unsigned)g, 253u);
            #pragma unroll
            for (int jj = 0; jj < 5; ++jj) {
                int o = lane + 32 * jj;
                int i = GF4 * g + o;
                if (o < GF4 && i < NH4) {
                    float4 b = vsm4[i];
                    FMA4(A0, __ldg(qA + 128 + i), b);
                    FMA4(A1, __ldg(qB + 128 + i), b);
                }
            }
        }
        float zA = warp_sum((A0.x + A0.y) + (A0.z + A0.w));
        float zB = warp_sum((A1.x + A1.y) + (A1.z + A1.w));

        if (lane < 2) {
            int r = rA + lane;
            float z  = (lane == 0) ? zA : zB;
            float hn = tanhf(z + __ldg(bi + min(r, NH - 1)));
            if (r < NH) out[NOUT + r] = hn;
            zbuf[2 * w + lane] = hn;
        }
        __syncthreads();                                // zbuf(hn) ready for gHn publish
    }

    // ---- h2o: CTA cb < 128 computes out[cb] with warp 0 ----
    if (cb < NOUT && w == 0) {
        const float4* pWo = (const float4*)Wo + (size_t)cb * NH4;
        float4 A = make_float4(0.f,0.f,0.f,0.f);
        #pragma unroll 1
        for (int g = 0; g < NG; ++g) {
            cnt_spin(cntA + 4u * (unsigned)g, 254u);
            #pragma unroll
            for (int jj = 0; jj < 5; ++jj) {
                int o = lane + 32 * jj;
                int i = GF4 * g + o;
                if (o < GF4 && i < NH4) {
                    FMA4(A, __ldg(pWo + i), vsm4[i]);
                }
            }
        }
        float z = warp_sum((A.x + A.y) + (A.z + A.w));
        if (lane == 0) out[cb] = z + __ldg(bo + cb);
    }
}

extern "C" void kernel_launch(void* const* d_in, const int* in_sizes, int n_in,
                              void* d_out, int out_size)
{
    const float* x   = (const float*)d_in[0];
    const float* h0  = (const float*)d_in[1];
    const float* t   = (const float*)d_in[2];
    const float* Wf  = (const float*)d_in[3];
    const float* bf  = (const float*)d_in[4];
    const float* Wi  = (const float*)d_in[5];
    const float* bi  = (const float*)d_in[6];
    const float* Wo  = (const float*)d_in[7];
    const float* bo  = (const float*)d_in[8];
    float* out = (float*)d_out;

    cudaFuncSetAttribute(ode_rnn_kernel,
                         cudaFuncAttributeMaxDynamicSharedMemorySize, SMEM_BYTES);
    ode_rnn_kernel<<<GRID, NTHREADS, SMEM_BYTES>>>(x, h0, t, Wf, bf, Wi, bi, Wo, bo, out);
}

// round 7
// speedup vs baseline: 2.5128x; 1.3714x over previous
#include <cuda_runtime.h>
#include <cstdint>

#define NH       4096
#define NH4      1024
#define NSTAGE   252                // 63 RK4 steps * 4 stages
#define NOUT     128
#define CMB4     1152

#define GRID     147
#define NW       14
#define NTHREADS 448
#define RPB      28                 // rows per CTA (2 per warp)
#define SW       13                 // rowA of warps 0..12 cached in SMEM

// smem: [13 Wf rows fp32 = 212992][v 16384][dt 256] = 229632 < 232448
#define OFF_VSM   212992
#define OFF_DT    229376
#define SMEM_BYTES 229632

__device__ __align__(16) float gV[2][4128];   // rows 0..4115 used (147*28)
__device__ __align__(16) float gHn[4128];
__device__ unsigned g_arrive;                 // single monotonic barrier counter

// arrive: CTA-wide sync, then one release-atomic; target derived from return.
__device__ __forceinline__ unsigned bar_arrive() {
    __syncthreads();
    unsigned target = 0;
    if (threadIdx.x == 0) {
        unsigned old;
        asm volatile("atom.add.release.gpu.u32 %0, [%1], 1;"
                     : "=r"(old) : "l"(&g_arrive) : "memory");
        target = old - old % GRID + GRID;     // end of current barrier round
    }
    return target;
}

__device__ __forceinline__ void bar_wait(unsigned target) {
    if (threadIdx.x == 0) {
        unsigned cur;
        do {
            asm volatile("ld.acquire.gpu.u32 %0, [%1];"
                         : "=r"(cur) : "l"(&g_arrive) : "memory");
        } while ((int)(cur - target) < 0);
    }
    __syncthreads();
}

__device__ __forceinline__ float warp_sum(float v) {
    #pragma unroll
    for (int o = 16; o; o >>= 1) v += __shfl_xor_sync(0xffffffffu, v, o);
    return v;
}

#define FMA4(A, Q, B) \
    { (A).x = fmaf((Q).x, (B).x, (A).x); (A).y = fmaf((Q).y, (B).y, (A).y); \
      (A).z = fmaf((Q).z, (B).z, (A).z); (A).w = fmaf((Q).w, (B).w, (A).w); }

__global__ void __launch_bounds__(NTHREADS, 1)
ode_rnn_kernel(const float* __restrict__ x,
               const float* __restrict__ h0,
               const float* __restrict__ t,
               const float* __restrict__ Wf,
               const float* __restrict__ bf,
               const float* __restrict__ Wi,
               const float* __restrict__ bi,
               const float* __restrict__ Wo,
               const float* __restrict__ bo,
               float* __restrict__ out)
{
    extern __shared__ char smem[];
    float4* wsm   = (float4*)smem;
    float4* vsm4  = (float4*)(smem + OFF_VSM);
    float*  dtbuf = (float*)(smem + OFF_DT);

    const int tid  = threadIdx.x;
    const int w    = tid >> 5;
    const int lane = tid & 31;
    const int base = blockIdx.x * RPB;

    const int rA  = base + 2 * w;               // even
    const int cAi = min(rA,     NH - 1);
    const int cBi = min(rA + 1, NH - 1);

    const float4* Wf4 = (const float4*)Wf;
    const float4* pA  = Wf4 + (size_t)cAi * NH4;
    const float4* pB  = Wf4 + (size_t)cBi * NH4;
    const float4* waS = wsm + (size_t)w * NH4;
    const bool lastw  = (w == NW - 1);

    // ---- SMEM preload: rowA of warps 0..12 ----
    for (int idx = tid; idx < SW * NH4; idx += NTHREADS) {
        int slot   = idx >> 10;
        int within = idx & 1023;
        int gr     = min(base + 2 * slot, NH - 1);
        wsm[idx]   = __ldg(Wf4 + (size_t)gr * NH4 + within);
    }
    if (tid < NSTAGE / 4) dtbuf[tid] = __ldg(t + tid + 1) - __ldg(t + tid);

    // register cache: rowB chunks 0..7
    float4 cacheB[8];
    #pragma unroll
    for (int k = 0; k < 8; ++k) cacheB[k] = __ldg(pB + lane + 32 * k);

    // replicated per-warp RK4 state (both rows, all lanes)
    float hhA = __ldg(h0 + cAi), hhB = __ldg(h0 + cBi);
    const float bfA = __ldg(bf + cAi), bfB = __ldg(bf + cBi);

    if (lane == 0)
        *(float2*)(&gV[0][rA]) = make_float2(hhA, hhB);

    float4 rb[6], ra[4];

    // first barrier; prefetch stage-0 rings in the window
    unsigned tgt = bar_arrive();
    if (!lastw) {
        #pragma unroll
        for (int j = 0; j < 6; ++j) rb[j] = __ldg(pB + lane + 32 * (8 + j));
    } else {
        #pragma unroll
        for (int j = 0; j < 4; ++j) { rb[j] = __ldg(pB + lane + 32 * (8 + j));
                                      ra[j] = __ldg(pA + lane + 32 * j); }
    }
    bar_wait(tgt);

    int p = 0;
    float k1A = 0.f, k2A = 0.f, k3A = 0.f;
    float k1B = 0.f, k2B = 0.f, k3B = 0.f;

    #pragma unroll 1
    for (int sg = 0; sg < NSTAGE; ++sg) {
        const float dt = dtbuf[sg >> 2];
        const int   u  = sg & 3;

        // ---- batched v-fill (MLP=3) ----
        {
            const float4* src = (const float4*)gV[p];
            float4 t0 = __ldcg(src + tid);
            float4 t1 = __ldcg(src + tid + NTHREADS);
            float4 t2;
            const bool g3 = tid < (NH4 - 2 * NTHREADS);
            if (g3) t2 = __ldcg(src + tid + 2 * NTHREADS);
            vsm4[tid] = t0;
            vsm4[tid + NTHREADS] = t1;
            if (g3) vsm4[tid + 2 * NTHREADS] = t2;
        }
        __syncthreads();

        float4 A0 = make_float4(0.f,0.f,0.f,0.f);
        float4 A1 = A0;

        if (!lastw) {
            #pragma unroll
            for (int k = 0; k < 8; ++k) {
                const int i = lane + 32 * k;
                float4 b = vsm4[i];
                FMA4(A0, waS[i], b);
                FMA4(A1, cacheB[k], b);
            }
            #pragma unroll
            for (int k = 8; k < 32; ++k) {
                const int i = lane + 32 * k;
                const int j = (k - 8) % 6;
                float4 b = vsm4[i];
                float4 q = rb[j];
                if (k < 26) rb[j] = __ldg(pB + i + 32 * 6);
                FMA4(A0, waS[i], b);
                FMA4(A1, q, b);
            }
        } else {
            #pragma unroll
            for (int k = 0; k < 8; ++k) {
                const int i = lane + 32 * k;
                float4 b  = vsm4[i];
                float4 qa = ra[k % 4];
                if (k < 28) ra[k % 4] = __ldg(pA + i + 32 * 4);
                FMA4(A0, qa, b);
                FMA4(A1, cacheB[k], b);
            }
            #pragma unroll
            for (int k = 8; k < 32; ++k) {
                const int i = lane + 32 * k;
                float4 b  = vsm4[i];
                float4 qa = ra[k % 4];
                float4 qb = rb[(k - 8) % 4];
                if (k < 28) { ra[k % 4]       = __ldg(pA + i + 32 * 4);
                              rb[(k - 8) % 4] = __ldg(pB + i + 32 * 4); }
                FMA4(A0, qa, b);
                FMA4(A1, qb, b);
            }
        }

        const float zA = warp_sum((A0.x + A0.y) + (A0.z + A0.w));
        const float zB = warp_sum((A1.x + A1.y) + (A1.z + A1.w));

        const float kA = tanhf(zA + bfA);
        const float kB = tanhf(zB + bfB);

        const float half = 0.5f * dt;
        float vA, vB;
        if (u == 0)      { k1A = kA; k1B = kB; vA = hhA + half * kA; vB = hhB + half * kB; }
        else if (u == 1) { k2A = kA; k2B = kB; vA = hhA + half * kA; vB = hhB + half * kB; }
        else if (u == 2) { k3A = kA; k3B = kB; vA = hhA + dt * kA;   vB = hhB + dt * kB; }
        else {
            const float c = dt * (1.0f / 6.0f);
            hhA = hhA + c * (k1A + 2.0f * k2A + 2.0f * k3A + kA);
            hhB = hhB + c * (k1B + 2.0f * k2B + 2.0f * k3B + kB);
            vA = hhA; vB = hhB;
        }
        if (lane == 0)
            *(float2*)(&gV[p ^ 1][rA]) = make_float2(vA, vB);

        // arrive, prefetch next stage's rings under the poll window, wait
        tgt = bar_arrive();
        if (!lastw) {
            #pragma unroll
            for (int j = 0; j < 6; ++j) rb[j] = __ldg(pB + lane + 32 * (8 + j));
        } else {
            #pragma unroll
            for (int j = 0; j < 4; ++j) { rb[j] = __ldg(pB + lane + 32 * (8 + j));
                                          ra[j] = __ldg(pA + lane + 32 * j); }
        }
        bar_wait(tgt);
        p ^= 1;
    }
    // hT is in gV[p] (p == 0 after 252 stages)

    // ---- i2h: h_new = tanh(W_i2h @ [x; hT] + b_i2h) ----
    {
        // fill vsm with hT
        const float4* src = (const float4*)gV[p];
        for (int i = tid; i < NH4; i += NTHREADS) vsm4[i] = __ldcg(src + i);
        __syncthreads();

        const float4* Wi4 = (const float4*)Wi;
        const float4* qA  = Wi4 + (size_t)cAi * CMB4;
        const float4* qB  = Wi4 + (size_t)cBi * CMB4;
        const float4* x4  = (const float4*)x;

        float4 A0 = make_float4(0.f,0.f,0.f,0.f);
        float4 A1 = A0;
        #pragma unroll
        for (int jj = 0; jj < 4; ++jj) {             // x part: 128 float4
            const int i = lane + 32 * jj;
            float4 b = __ldg(x4 + i);
            FMA4(A0, __ldg(qA + i), b);
            FMA4(A1, __ldg(qB + i), b);
        }
        #pragma unroll 4
        for (int k = 0; k < 32; ++k) {               // h part: 1024 float4
            const int i = lane + 32 * k;
            float4 b = vsm4[i];
            FMA4(A0, __ldg(qA + 128 + i), b);
            FMA4(A1, __ldg(qB + 128 + i), b);
        }
        const float zA = warp_sum((A0.x + A0.y) + (A0.z + A0.w));
        const float zB = warp_sum((A1.x + A1.y) + (A1.z + A1.w));

        const float hnA = tanhf(zA + __ldg(bi + cAi));
        const float hnB = tanhf(zB + __ldg(bi + cBi));
        if (lane == 0) {
            *(float2*)(&gHn[rA])        = make_float2(hnA, hnB);
            *(float2*)(&out[NOUT + rA]) = make_float2(hnA, hnB);
        }
    }
    tgt = bar_arrive();
    bar_wait(tgt);

    // ---- h2o: out[0..127] = W_h2o @ h_new + b_h2o (CTA cb<128, warp 0) ----
    if (blockIdx.x < NOUT && w == 0) {
        const int cb = blockIdx.x;
        const float4* pWo = (const float4*)Wo + (size_t)cb * NH4;
        const float4* hv  = (const float4*)gHn;
        float4 A = make_float4(0.f,0.f,0.f,0.f);
        #pragma unroll 4
        for (int k = 0; k < 32; ++k) {
            const int i = lane + 32 * k;
            FMA4(A, __ldg(pWo + i), __ldcg(hv + i));
        }
        const float z = warp_sum((A.x + A.y) + (A.z + A.w));
        if (lane == 0) out[cb] = z + __ldg(bo + cb);
    }
}

extern "C" void kernel_launch(void* const* d_in, const int* in_sizes, int n_in,
                              void* d_out, int out_size)
{
    const float* x   = (const float*)d_in[0];
    const float* h0  = (const float*)d_in[1];
    const float* t   = (const float*)d_in[2];
    const float* Wf  = (const float*)d_in[3];
    const float* bf  = (const float*)d_in[4];
    const float* Wi  = (const float*)d_in[5];
    const float* bi  = (const float*)d_in[6];
    const float* Wo  = (const float*)d_in[7];
    const float* bo  = (const float*)d_in[8];
    float* out = (float*)d_out;

    cudaFuncSetAttribute(ode_rnn_kernel,
                         cudaFuncAttributeMaxDynamicSharedMemorySize, SMEM_BYTES);
    ode_rnn_kernel<<<GRID, NTHREADS, SMEM_BYTES>>>(x, h0, t, Wf, bf, Wi, bi, Wo, bo, out);
}